// round 16
// baseline (speedup 1.0000x reference)
#include <cuda_runtime.h>
#include <cuda_bf16.h>
#include <math.h>
#include <stdint.h>

// ---------------------------------------------------------------------------
// Problem constants
// ---------------------------------------------------------------------------
#define NF   128          // frames
#define PP   576          // patches
#define DD   1536         // feature dim
#define LM   4096
#define NQ   64
#define PG   9            // patches per pool group (576/64)
#define NM1  127          // N-1
#define NCUBES 8
#define SPLITK 8          // for the two D x D GEMMs
#define SPLITK3 4         // for the thumbnail GEMM

#define OUT_GATE 0
#define OUT_TH   254
#define OUT_Z    (254 + NQ * LM)   // 262398

// ---------------------------------------------------------------------------
// Scratch (static __device__ arrays; no allocation)
// ---------------------------------------------------------------------------
__device__ float g_framemean[NF * DD];
__device__ float g_mommean[NF * DD];                  // rows 0..126 used
__device__ float g_xn[NF * DD];
__device__ float g_pooled[NQ * DD];
__device__ float g_part[SPLITK * NQ * LM];            // split-K partials (8 MB)
__device__ float g_y[NM1];
__device__ int   g_selidx[PG];
__device__ float g_selw[PG];
__device__ float g_scale;

// ---------------------------------------------------------------------------
// tf32 helpers
// ---------------------------------------------------------------------------
__device__ __forceinline__ float f2tf32(float x) {
    uint32_t u;
    asm("cvt.rna.tf32.f32 %0, %1;" : "=r"(u) : "f"(x));
    return __uint_as_float(u);
}

#define MMA_TF32(dreg, a, b0, b1)                                              \
    asm volatile(                                                              \
        "mma.sync.aligned.m16n8k8.row.col.f32.tf32.tf32.f32 "                  \
        "{%0,%1,%2,%3}, {%4,%5,%6,%7}, {%8,%9}, {%0,%1,%2,%3};"                \
        : "+f"(dreg[0]), "+f"(dreg[1]), "+f"(dreg[2]), "+f"(dreg[3])           \
        : "r"(a[0]), "r"(a[1]), "r"(a[2]), "r"(a[3]), "r"(b0), "r"(b1))

// ---------------------------------------------------------------------------
// K1: one streaming pass over video_features -> framemean[n][d]
// ---------------------------------------------------------------------------
__global__ void __launch_bounds__(256) framesum_kernel(const float* __restrict__ vf) {
    int n = blockIdx.x;
    int col = blockIdx.y * 128 + (threadIdx.x & 127);   // float4 column 0..383
    int half = threadIdx.x >> 7;                         // 0 or 1
    const float4* base = (const float4*)(vf + (size_t)n * PP * DD) + col;
    float4 s = make_float4(0.f, 0.f, 0.f, 0.f);
#pragma unroll 8
    for (int p = half; p < PP; p += 2) {
        float4 v = base[(size_t)p * (DD / 4)];
        s.x += v.x; s.y += v.y; s.z += v.z; s.w += v.w;
    }
    __shared__ float4 sh[128];
    if (half == 1) sh[threadIdx.x & 127] = s;
    __syncthreads();
    if (half == 0) {
        float4 o = sh[threadIdx.x];
        const float inv = 1.0f / (float)PP;
        s.x = (s.x + o.x) * inv;
        s.y = (s.y + o.y) * inv;
        s.z = (s.z + o.z) * inv;
        s.w = (s.w + o.w) * inv;
        ((float4*)(g_framemean + n * DD))[col] = s;
    }
}

// ---------------------------------------------------------------------------
// K2: windowed-parallel momentum EMA scan (0.5^40 truncation ~9e-13)
// ---------------------------------------------------------------------------
#define SCAN_SEG 8
#define SCAN_WIN 40
__global__ void __launch_bounds__(384) scan_kernel() {
    int b = blockIdx.x;
    int s = b * SCAN_SEG;
    int c4 = threadIdx.x;                     // float4 col 0..383
    const float4* fm = (const float4*)g_framemean;
    float4* mom = (float4*)g_mommean;

    float4 m;
    int istart;
    if (b == 0) {
        float4 f0 = fm[c4];
        float4 f1 = fm[384 + c4];
        m = make_float4(f1.x - f0.x, f1.y - f0.y, f1.z - f0.z, f1.w - f0.w);
        mom[c4] = m;
        istart = 1;
    } else {
        int istar = s - 1;
        int jlo = istar - (SCAN_WIN - 1); if (jlo < 0) jlo = 0;
        float w = 0.5f;
        float4 acc = make_float4(0.f, 0.f, 0.f, 0.f);
#pragma unroll 8
        for (int j = istar; j >= jlo; j--) {
            float4 fa = fm[(size_t)j * 384 + c4];
            float4 fb = fm[(size_t)(j + 1) * 384 + c4];
            acc.x = fmaf(w, fb.x - fa.x, acc.x);
            acc.y = fmaf(w, fb.y - fa.y, acc.y);
            acc.z = fmaf(w, fb.z - fa.z, acc.z);
            acc.w = fmaf(w, fb.w - fa.w, acc.w);
            if (j >= 2) w *= 0.5f;            // diff[0] shares diff[1]'s weight
        }
        m = acc;
        istart = s;
    }
#pragma unroll
    for (int i0 = 0; i0 < SCAN_SEG; i0++) {
        int i = (b == 0) ? (istart + i0) : (s + i0);
        if (i >= NM1) break;
        if (b == 0 && i0 >= SCAN_SEG - 1 && istart + i0 >= SCAN_SEG) break;
        if (i < istart) continue;
        float4 fa = fm[(size_t)i * 384 + c4];
        float4 fb = fm[(size_t)(i + 1) * 384 + c4];
        m.x = 0.5f * (fb.x - fa.x) + 0.5f * m.x;
        m.y = 0.5f * (fb.y - fa.y) + 0.5f * m.y;
        m.z = 0.5f * (fb.z - fa.z) + 0.5f * m.z;
        m.w = 0.5f * (fb.w - fa.w) + 0.5f * m.w;
        mom[(size_t)i * 384 + c4] = m;
    }
}

// ---------------------------------------------------------------------------
// tf32 tensor-core split-K GEMM, 3-term hi/lo compensation (fp32-accurate).
// BM=64, BN=64, BK=32, 256 threads, 8 warps (4m x 2n), warp = 16x32 out.
// Used for the gate chain (top-k selection must not flip).
// ---------------------------------------------------------------------------
#define GBM 64
#define GBN 64
#define GBK 32
#define ASTR (GBK + 4)    // 36
#define BSTR (GBN + 4)    // 68

__global__ void __launch_bounds__(256) gemm_tf32_splitk(
    const float* __restrict__ A, const float* __restrict__ B,
    float* __restrict__ Cpart, int M, int N, int K)
{
    __shared__ float As_hi[2][GBM][ASTR];
    __shared__ float As_lo[2][GBM][ASTR];
    __shared__ float Bs_hi[2][GBK][BSTR];
    __shared__ float Bs_lo[2][GBK][BSTR];

    int tid = threadIdx.x;
    int lane = tid & 31, wid = tid >> 5;
    int wm = (wid & 3) * 16;
    int wn = (wid >> 2) * 32;
    int g = lane >> 2, t = lane & 3;

    int n0 = blockIdx.x * GBN;
    int m0 = blockIdx.y * GBM;
    int kchunk = K / gridDim.z;
    int k0 = blockIdx.z * kchunk;
    int ksteps = kchunk / GBK;

    int ar = tid >> 2;              // 0..63
    int ac = (tid & 3) * 4;         // 0,4,8,12 ; second at +16
    int br = tid >> 4;              // 0..15    ; second at +16
    int bc = (tid & 15) * 4;        // 0..60

    bool a_ok = (m0 + ar) < M;
    const float* Aptr = A + (size_t)(m0 + ar) * K + k0;
    const float* Bptr = B + (size_t)(k0 + br) * N + n0 + bc;

    float d[4][4];
#pragma unroll
    for (int j = 0; j < 4; j++)
#pragma unroll
        for (int i = 0; i < 4; i++) d[j][i] = 0.f;

    float4 a_pre0, a_pre1, b_pre0, b_pre1;

    auto fetch = [&](int kt) {
        const float* ap = Aptr + kt * GBK;
        a_pre0 = a_ok ? *(const float4*)(ap + ac)      : make_float4(0.f, 0.f, 0.f, 0.f);
        a_pre1 = a_ok ? *(const float4*)(ap + ac + 16) : make_float4(0.f, 0.f, 0.f, 0.f);
        const float* bp = Bptr + (size_t)kt * GBK * N;
        b_pre0 = *(const float4*)bp;
        b_pre1 = *(const float4*)(bp + (size_t)16 * N);
    };
    auto stage = [&](int buf) {
        float4 av = a_pre0;
        float h0 = f2tf32(av.x), h1 = f2tf32(av.y), h2 = f2tf32(av.z), h3 = f2tf32(av.w);
        *(float4*)&As_hi[buf][ar][ac] = make_float4(h0, h1, h2, h3);
        *(float4*)&As_lo[buf][ar][ac] =
            make_float4(f2tf32(av.x - h0), f2tf32(av.y - h1),
                        f2tf32(av.z - h2), f2tf32(av.w - h3));
        av = a_pre1;
        h0 = f2tf32(av.x); h1 = f2tf32(av.y); h2 = f2tf32(av.z); h3 = f2tf32(av.w);
        *(float4*)&As_hi[buf][ar][ac + 16] = make_float4(h0, h1, h2, h3);
        *(float4*)&As_lo[buf][ar][ac + 16] =
            make_float4(f2tf32(av.x - h0), f2tf32(av.y - h1),
                        f2tf32(av.z - h2), f2tf32(av.w - h3));
        float4 bv = b_pre0;
        float p0 = f2tf32(bv.x), p1 = f2tf32(bv.y), p2 = f2tf32(bv.z), p3 = f2tf32(bv.w);
        *(float4*)&Bs_hi[buf][br][bc] = make_float4(p0, p1, p2, p3);
        *(float4*)&Bs_lo[buf][br][bc] =
            make_float4(f2tf32(bv.x - p0), f2tf32(bv.y - p1),
                        f2tf32(bv.z - p2), f2tf32(bv.w - p3));
        bv = b_pre1;
        p0 = f2tf32(bv.x); p1 = f2tf32(bv.y); p2 = f2tf32(bv.z); p3 = f2tf32(bv.w);
        *(float4*)&Bs_hi[buf][br + 16][bc] = make_float4(p0, p1, p2, p3);
        *(float4*)&Bs_lo[buf][br + 16][bc] =
            make_float4(f2tf32(bv.x - p0), f2tf32(bv.y - p1),
                        f2tf32(bv.z - p2), f2tf32(bv.w - p3));
    };

    fetch(0);
    stage(0);
    __syncthreads();

    for (int kt = 0; kt < ksteps; kt++) {
        int cur = kt & 1;
        if (kt + 1 < ksteps) fetch(kt + 1);
#pragma unroll
        for (int ks = 0; ks < 4; ks++) {
            int kk = ks * 8;
            uint32_t ah[4], al[4];
            ah[0] = __float_as_uint(As_hi[cur][wm + g    ][kk + t    ]);
            ah[1] = __float_as_uint(As_hi[cur][wm + g + 8][kk + t    ]);
            ah[2] = __float_as_uint(As_hi[cur][wm + g    ][kk + t + 4]);
            ah[3] = __float_as_uint(As_hi[cur][wm + g + 8][kk + t + 4]);
            al[0] = __float_as_uint(As_lo[cur][wm + g    ][kk + t    ]);
            al[1] = __float_as_uint(As_lo[cur][wm + g + 8][kk + t    ]);
            al[2] = __float_as_uint(As_lo[cur][wm + g    ][kk + t + 4]);
            al[3] = __float_as_uint(As_lo[cur][wm + g + 8][kk + t + 4]);
#pragma unroll
            for (int j = 0; j < 4; j++) {
                int n = wn + j * 8 + g;
                uint32_t bh0 = __float_as_uint(Bs_hi[cur][kk + t    ][n]);
                uint32_t bh1 = __float_as_uint(Bs_hi[cur][kk + t + 4][n]);
                uint32_t bl0 = __float_as_uint(Bs_lo[cur][kk + t    ][n]);
                uint32_t bl1 = __float_as_uint(Bs_lo[cur][kk + t + 4][n]);
                MMA_TF32(d[j], ah, bh0, bh1);   // hi*hi
                MMA_TF32(d[j], ah, bl0, bl1);   // hi*lo
                MMA_TF32(d[j], al, bh0, bh1);   // lo*hi
            }
        }
        if (kt + 1 < ksteps) {
            stage(cur ^ 1);
            __syncthreads();
        }
    }

    size_t MN = (size_t)M * N;
    float* Cb = Cpart + (size_t)blockIdx.z * MN;
#pragma unroll
    for (int j = 0; j < 4; j++) {
        int col = n0 + wn + j * 8 + 2 * t;
        int r0 = m0 + wm + g;
        if (r0 < M) *(float2*)&Cb[(size_t)r0 * N + col] = make_float2(d[j][0], d[j][1]);
        int r1 = r0 + 8;
        if (r1 < M) *(float2*)&Cb[(size_t)r1 * N + col] = make_float2(d[j][2], d[j][3]);
    }
}

// ---------------------------------------------------------------------------
// Single-term tf32 split-K GEMM (no hi/lo): ~2e-4 rel err, 3x fewer mma,
// half the smem and staging work. Used for the thumbnail GEMM only
// (analog output, 10x inside the 1e-3 threshold; cannot flip top-k).
// ---------------------------------------------------------------------------
__global__ void __launch_bounds__(256) gemm_tf32_1term(
    const float* __restrict__ A, const float* __restrict__ B,
    float* __restrict__ Cpart, int M, int N, int K)
{
    __shared__ float As_hi[2][GBM][ASTR];
    __shared__ float Bs_hi[2][GBK][BSTR];

    int tid = threadIdx.x;
    int lane = tid & 31, wid = tid >> 5;
    int wm = (wid & 3) * 16;
    int wn = (wid >> 2) * 32;
    int g = lane >> 2, t = lane & 3;

    int n0 = blockIdx.x * GBN;
    int m0 = blockIdx.y * GBM;
    int kchunk = K / gridDim.z;
    int k0 = blockIdx.z * kchunk;
    int ksteps = kchunk / GBK;

    int ar = tid >> 2;
    int ac = (tid & 3) * 4;
    int br = tid >> 4;
    int bc = (tid & 15) * 4;

    bool a_ok = (m0 + ar) < M;
    const float* Aptr = A + (size_t)(m0 + ar) * K + k0;
    const float* Bptr = B + (size_t)(k0 + br) * N + n0 + bc;

    float d[4][4];
#pragma unroll
    for (int j = 0; j < 4; j++)
#pragma unroll
        for (int i = 0; i < 4; i++) d[j][i] = 0.f;

    float4 a_pre0, a_pre1, b_pre0, b_pre1;

    auto fetch = [&](int kt) {
        const float* ap = Aptr + kt * GBK;
        a_pre0 = a_ok ? *(const float4*)(ap + ac)      : make_float4(0.f, 0.f, 0.f, 0.f);
        a_pre1 = a_ok ? *(const float4*)(ap + ac + 16) : make_float4(0.f, 0.f, 0.f, 0.f);
        const float* bp = Bptr + (size_t)kt * GBK * N;
        b_pre0 = *(const float4*)bp;
        b_pre1 = *(const float4*)(bp + (size_t)16 * N);
    };
    auto stage = [&](int buf) {
        *(float4*)&As_hi[buf][ar][ac] =
            make_float4(f2tf32(a_pre0.x), f2tf32(a_pre0.y), f2tf32(a_pre0.z), f2tf32(a_pre0.w));
        *(float4*)&As_hi[buf][ar][ac + 16] =
            make_float4(f2tf32(a_pre1.x), f2tf32(a_pre1.y), f2tf32(a_pre1.z), f2tf32(a_pre1.w));
        *(float4*)&Bs_hi[buf][br][bc] =
            make_float4(f2tf32(b_pre0.x), f2tf32(b_pre0.y), f2tf32(b_pre0.z), f2tf32(b_pre0.w));
        *(float4*)&Bs_hi[buf][br + 16][bc] =
            make_float4(f2tf32(b_pre1.x), f2tf32(b_pre1.y), f2tf32(b_pre1.z), f2tf32(b_pre1.w));
    };

    fetch(0);
    stage(0);
    __syncthreads();

    for (int kt = 0; kt < ksteps; kt++) {
        int cur = kt & 1;
        if (kt + 1 < ksteps) fetch(kt + 1);
#pragma unroll
        for (int ks = 0; ks < 4; ks++) {
            int kk = ks * 8;
            uint32_t ah[4];
            ah[0] = __float_as_uint(As_hi[cur][wm + g    ][kk + t    ]);
            ah[1] = __float_as_uint(As_hi[cur][wm + g + 8][kk + t    ]);
            ah[2] = __float_as_uint(As_hi[cur][wm + g    ][kk + t + 4]);
            ah[3] = __float_as_uint(As_hi[cur][wm + g + 8][kk + t + 4]);
#pragma unroll
            for (int j = 0; j < 4; j++) {
                int n = wn + j * 8 + g;
                uint32_t bh0 = __float_as_uint(Bs_hi[cur][kk + t    ][n]);
                uint32_t bh1 = __float_as_uint(Bs_hi[cur][kk + t + 4][n]);
                MMA_TF32(d[j], ah, bh0, bh1);
            }
        }
        if (kt + 1 < ksteps) {
            stage(cur ^ 1);
            __syncthreads();
        }
    }

    size_t MN = (size_t)M * N;
    float* Cb = Cpart + (size_t)blockIdx.z * MN;
#pragma unroll
    for (int j = 0; j < 4; j++) {
        int col = n0 + wn + j * 8 + 2 * t;
        int r0 = m0 + wm + g;
        if (r0 < M) *(float2*)&Cb[(size_t)r0 * N + col] = make_float2(d[j][0], d[j][1]);
        int r1 = r0 + 8;
        if (r1 < M) *(float2*)&Cb[(size_t)r1 * N + col] = make_float2(d[j][2], d[j][3]);
    }
}

// ---------------------------------------------------------------------------
// Fused: combine split-K partials (+b_agg) -> LayerNorm -> g_xn.
// ---------------------------------------------------------------------------
__global__ void __launch_bounds__(512) ln_combine_kernel(
    const float* __restrict__ part, const float* __restrict__ b_agg,
    const float* __restrict__ ln_g, const float* __restrict__ ln_b)
{
    int row = blockIdx.x;
    const size_t MN = (size_t)NM1 * DD;
    const float* base = part + (size_t)row * DD;
    float v[3];
    float s = 0.f, ss = 0.f;
#pragma unroll
    for (int c = 0; c < 3; c++) {
        int col = threadIdx.x + c * 512;
        float a = b_agg[col];
#pragma unroll
        for (int z = 0; z < SPLITK; z++) a += base[(size_t)z * MN + col];
        v[c] = a;
        s += a;
        ss = fmaf(a, a, ss);
    }
    __shared__ float sh1[16], sh2[16];
    int lane = threadIdx.x & 31, w = threadIdx.x >> 5;
#pragma unroll
    for (int o = 16; o; o >>= 1) {
        s  += __shfl_xor_sync(0xFFFFFFFFu, s, o);
        ss += __shfl_xor_sync(0xFFFFFFFFu, ss, o);
    }
    if (lane == 0) { sh1[w] = s; sh2[w] = ss; }
    __syncthreads();
    if (w == 0) {
        s  = (lane < 16) ? sh1[lane] : 0.f;
        ss = (lane < 16) ? sh2[lane] : 0.f;
#pragma unroll
        for (int o = 8; o; o >>= 1) {
            s  += __shfl_xor_sync(0xFFFFFFFFu, s, o);
            ss += __shfl_xor_sync(0xFFFFFFFFu, ss, o);
        }
        if (lane == 0) { sh1[0] = s; sh2[0] = ss; }
    }
    __syncthreads();
    float mu  = sh1[0] * (1.0f / DD);
    float var = sh2[0] * (1.0f / DD) - mu * mu;
    float rstd = rsqrtf(var + 1e-5f);
#pragma unroll
    for (int c = 0; c < 3; c++) {
        int col = threadIdx.x + c * 512;
        g_xn[row * DD + col] = (v[c] - mu) * rstd * ln_g[col] + ln_b[col];
    }
}

// ---------------------------------------------------------------------------
// Fused: combine split-K partials (+b1) -> GELU -> dot W2 (+b2) ->
// gate logits (out) + gumbel-softmax y (g_y).
// ---------------------------------------------------------------------------
__global__ void __launch_bounds__(512) gate_combine_kernel(
    const float* __restrict__ part, const float* __restrict__ b1,
    const float* __restrict__ W2, const float* __restrict__ b2,
    const float* __restrict__ gu, float* __restrict__ out)
{
    int row = blockIdx.x;
    const size_t MN = (size_t)NM1 * DD;
    const float* base = part + (size_t)row * DD;
    float s0 = 0.f, s1 = 0.f;
#pragma unroll
    for (int c = 0; c < 3; c++) {
        int col = threadIdx.x + c * 512;
        float a = b1[col];
#pragma unroll
        for (int z = 0; z < SPLITK; z++) a += base[(size_t)z * MN + col];
        a = 0.5f * a * (1.0f + erff(a * 0.70710678118654752f));   // exact GELU
        float2 w2 = *(const float2*)&W2[col * 2];
        s0 = fmaf(a, w2.x, s0);
        s1 = fmaf(a, w2.y, s1);
    }
    __shared__ float sh0[16], sh1w[16];
    int lane = threadIdx.x & 31, w = threadIdx.x >> 5;
#pragma unroll
    for (int o = 16; o; o >>= 1) {
        s0 += __shfl_xor_sync(0xFFFFFFFFu, s0, o);
        s1 += __shfl_xor_sync(0xFFFFFFFFu, s1, o);
    }
    if (lane == 0) { sh0[w] = s0; sh1w[w] = s1; }
    __syncthreads();
    if (threadIdx.x == 0) {
        float l0 = b2[0], l1 = b2[1];
#pragma unroll
        for (int i = 0; i < 16; i++) { l0 += sh0[i]; l1 += sh1w[i]; }
        out[OUT_GATE + row * 2 + 0] = l0;
        out[OUT_GATE + row * 2 + 1] = l1;
        float u0 = gu[row * 2 + 0], u1 = gu[row * 2 + 1];
        float g0 = -logf(-logf(u0 + 1e-20f) + 1e-20f);
        float g1 = -logf(-logf(u1 + 1e-20f) + 1e-20f);
        float a0 = (l0 + g0 * 0.1f) * 2.0f;   // / TEMP(0.5)
        float a1 = (l1 + g1 * 0.1f) * 2.0f;
        float mx = fmaxf(a0, a1);
        float e0 = expf(a0 - mx), e1 = expf(a1 - mx);
        g_y[row] = e1 / (e0 + e1);
    }
}

// ---------------------------------------------------------------------------
// Top-8 selection (stable), z_hard, weights
// ---------------------------------------------------------------------------
__global__ void __launch_bounds__(128) topk_kernel(float* __restrict__ out) {
    __shared__ float yv[128];
    __shared__ float rv[128];
    __shared__ int   ri[128];
    __shared__ int   taken[128];
    int t = threadIdx.x;
    yv[t] = (t < NM1) ? g_y[t] : -1e30f;
    taken[t] = 0;
    __syncthreads();
    for (int it = 0; it < NCUBES; it++) {
        rv[t] = taken[t] ? -1e30f : yv[t];
        ri[t] = t;
        __syncthreads();
        for (int off = 64; off > 0; off >>= 1) {
            if (t < off) {
                float v2 = rv[t + off]; int i2 = ri[t + off];
                if (v2 > rv[t] || (v2 == rv[t] && i2 < ri[t])) { rv[t] = v2; ri[t] = i2; }
            }
            __syncthreads();
        }
        if (t == 0) taken[ri[0]] = 1;
        __syncthreads();
    }
    float z = 0.f;
    if (t < NM1) z = taken[t] ? ((1.0f - yv[t]) + yv[t]) : 0.0f;
    if (t == 0) out[OUT_Z] = 1.0f;
    if (t < NM1) out[OUT_Z + 1 + t] = z;
    rv[t] = z;
    __syncthreads();
    for (int off = 64; off > 0; off >>= 1) {
        if (t < off) rv[t] += rv[t + off];
        __syncthreads();
    }
    if (t == 0) {
        float zsum = 1.0f + rv[0];
        g_scale = 1.0f / ((float)PG * zsum);
        g_selidx[0] = 0; g_selw[0] = 1.0f;
        int c = 1;
        for (int i = 0; i < NM1; i++) {
            if (taken[i]) {
                g_selidx[c] = i + 1;
                g_selw[c] = (1.0f - yv[i]) + yv[i];
                c++;
            }
        }
    }
}

// ---------------------------------------------------------------------------
// pooled[g][d] = scale * sum_k w_k * sum_{p in group g} vf[sel_k][p][d]
// ---------------------------------------------------------------------------
__global__ void __launch_bounds__(128) pooled_kernel(const float* __restrict__ vf) {
    int g = blockIdx.x;
    int d4 = blockIdx.y * 128 + threadIdx.x;   // 0..383
    int   sidx[PG];
    float sw[PG];
#pragma unroll
    for (int k = 0; k < PG; k++) { sidx[k] = g_selidx[k]; sw[k] = g_selw[k]; }
    float4 acc = make_float4(0.f, 0.f, 0.f, 0.f);
#pragma unroll
    for (int k = 0; k < PG; k++) {
        const float4* base =
            (const float4*)(vf + ((size_t)sidx[k] * PP + (size_t)g * PG) * DD) + d4;
        float w = sw[k];
#pragma unroll
        for (int r = 0; r < PG; r++) {
            float4 v = base[(size_t)r * (DD / 4)];
            acc.x = fmaf(w, v.x, acc.x);
            acc.y = fmaf(w, v.y, acc.y);
            acc.z = fmaf(w, v.z, acc.z);
            acc.w = fmaf(w, v.w, acc.w);
        }
    }
    float sc = g_scale;
    acc.x *= sc; acc.y *= sc; acc.z *= sc; acc.w *= sc;
    ((float4*)(g_pooled + g * DD))[d4] = acc;
}

// ---------------------------------------------------------------------------
// Thumbnail combine (SPLITK3 partials): float2-vectorized
// ---------------------------------------------------------------------------
__global__ void __launch_bounds__(256) combine_th_kernel(
    const float* __restrict__ part, const float* __restrict__ bias,
    float* __restrict__ dst)
{
    int idx = blockIdx.x * blockDim.x + threadIdx.x;   // float2 index
    const int total2 = NQ * LM / 2;
    if (idx >= total2) return;
    int col2 = idx & (LM / 2 - 1);
    float2 v = *(const float2*)&bias[col2 * 2];
    const float2* p2 = (const float2*)part;
#pragma unroll
    for (int z = 0; z < SPLITK3; z++) {
        float2 a = p2[(size_t)z * total2 + idx];
        v.x += a.x; v.y += a.y;
    }
    *(float2*)&dst[idx * 2] = v;
}

// ---------------------------------------------------------------------------
// launch
// ---------------------------------------------------------------------------
extern "C" void kernel_launch(void* const* d_in, const int* in_sizes, int n_in,
                              void* d_out, int out_size) {
    const float* vf    = (const float*)d_in[0];
    const float* gu    = (const float*)d_in[1];
    const float* W_agg = (const float*)d_in[2];
    const float* b_agg = (const float*)d_in[3];
    const float* ln_g  = (const float*)d_in[4];
    const float* ln_b  = (const float*)d_in[5];
    const float* W1    = (const float*)d_in[6];
    const float* b1    = (const float*)d_in[7];
    const float* W2    = (const float*)d_in[8];
    const float* b2    = (const float*)d_in[9];
    const float* W_th  = (const float*)d_in[10];
    const float* b_th  = (const float*)d_in[11];
    float* out = (float*)d_out;

    float* d_part;   cudaGetSymbolAddress((void**)&d_part,   g_part);
    float* d_mom;    cudaGetSymbolAddress((void**)&d_mom,    g_mommean);
    float* d_xn;     cudaGetSymbolAddress((void**)&d_xn,     g_xn);
    float* d_pooled; cudaGetSymbolAddress((void**)&d_pooled, g_pooled);

    // 1) stream video features once -> framemean
    framesum_kernel<<<dim3(NF, 3), 256>>>(vf);
    // 2) windowed-parallel momentum EMA scan
    scan_kernel<<<16, 384>>>();
    // 3) feat partials = mommean @ W_agg   (tf32 TC 3-term, split-K=8)
    gemm_tf32_splitk<<<dim3(DD / GBN, 2, SPLITK), 256>>>(d_mom, W_agg, d_part, NM1, DD, DD);
    // 4) combine + bias + LayerNorm -> xn
    ln_combine_kernel<<<NM1, 512>>>(d_part, b_agg, ln_g, ln_b);
    // 5) h partials = xn @ W1   (3-term)
    gemm_tf32_splitk<<<dim3(DD / GBN, 2, SPLITK), 256>>>(d_xn, W1, d_part, NM1, DD, DD);
    // 6) combine + bias + GELU + gate head + gumbel y
    gate_combine_kernel<<<NM1, 512>>>(d_part, b1, W2, b2, gu, out);
    // 7) top-8 + z_hard
    topk_kernel<<<1, 128>>>(out);
    // 8) pooled from selected frames (direct vf gather)
    pooled_kernel<<<dim3(NQ, 3), 128>>>(vf);
    // 9) thumbnail partials = pooled @ W_th  (single-term tf32, split-K=4)
    gemm_tf32_1term<<<dim3(LM / GBN, 1, SPLITK3), 256>>>(d_pooled, W_th, d_part, NQ, LM, DD);
    // 10) combine + bias -> out
    combine_th_kernel<<<(NQ * LM / 2 + 255) / 256, 256>>>(d_part, b_th, out + OUT_TH);
}

// round 17
// speedup vs baseline: 1.1431x; 1.1431x over previous
#include <cuda_runtime.h>
#include <cuda_bf16.h>
#include <math.h>
#include <stdint.h>

// ---------------------------------------------------------------------------
// Problem constants
// ---------------------------------------------------------------------------
#define NF   128          // frames
#define PP   576          // patches
#define DD   1536         // feature dim
#define LM   4096
#define NQ   64
#define PG   9            // patches per pool group (576/64)
#define NM1  127          // N-1
#define NCUBES 8
#define SPLITK 8          // for the two D x D GEMMs
#define SPLITK3 4         // for the thumbnail GEMM

#define OUT_GATE 0
#define OUT_TH   254
#define OUT_Z    (254 + NQ * LM)   // 262398

// ---------------------------------------------------------------------------
// Scratch (static __device__ arrays; no allocation)
// ---------------------------------------------------------------------------
__device__ float g_framemean[NF * DD];
__device__ float g_mommean[NF * DD];                  // rows 0..126 used
__device__ float g_xn[NF * DD];
__device__ float g_pooled[NQ * DD];
__device__ float g_part[SPLITK * NQ * LM];            // split-K partials (8 MB)
__device__ float g_y[NM1];

// ---------------------------------------------------------------------------
// tf32 helpers
// ---------------------------------------------------------------------------
__device__ __forceinline__ float f2tf32(float x) {
    uint32_t u;
    asm("cvt.rna.tf32.f32 %0, %1;" : "=r"(u) : "f"(x));
    return __uint_as_float(u);
}

#define MMA_TF32(dreg, a, b0, b1)                                              \
    asm volatile(                                                              \
        "mma.sync.aligned.m16n8k8.row.col.f32.tf32.tf32.f32 "                  \
        "{%0,%1,%2,%3}, {%4,%5,%6,%7}, {%8,%9}, {%0,%1,%2,%3};"                \
        : "+f"(dreg[0]), "+f"(dreg[1]), "+f"(dreg[2]), "+f"(dreg[3])           \
        : "r"(a[0]), "r"(a[1]), "r"(a[2]), "r"(a[3]), "r"(b0), "r"(b1))

// ---------------------------------------------------------------------------
// K1: one streaming pass over video_features -> framemean[n][d]
// ---------------------------------------------------------------------------
__global__ void __launch_bounds__(256) framesum_kernel(const float* __restrict__ vf) {
    int n = blockIdx.x;
    int col = blockIdx.y * 128 + (threadIdx.x & 127);   // float4 column 0..383
    int half = threadIdx.x >> 7;                         // 0 or 1
    const float4* base = (const float4*)(vf + (size_t)n * PP * DD) + col;
    float4 s = make_float4(0.f, 0.f, 0.f, 0.f);
#pragma unroll 8
    for (int p = half; p < PP; p += 2) {
        float4 v = base[(size_t)p * (DD / 4)];
        s.x += v.x; s.y += v.y; s.z += v.z; s.w += v.w;
    }
    __shared__ float4 sh[128];
    if (half == 1) sh[threadIdx.x & 127] = s;
    __syncthreads();
    if (half == 0) {
        float4 o = sh[threadIdx.x];
        const float inv = 1.0f / (float)PP;
        s.x = (s.x + o.x) * inv;
        s.y = (s.y + o.y) * inv;
        s.z = (s.z + o.z) * inv;
        s.w = (s.w + o.w) * inv;
        ((float4*)(g_framemean + n * DD))[col] = s;
    }
}

// ---------------------------------------------------------------------------
// K2: windowed-parallel momentum EMA scan (0.5^40 truncation ~9e-13)
// ---------------------------------------------------------------------------
#define SCAN_SEG 8
#define SCAN_WIN 40
__global__ void __launch_bounds__(384) scan_kernel() {
    int b = blockIdx.x;
    int s = b * SCAN_SEG;
    int c4 = threadIdx.x;                     // float4 col 0..383
    const float4* fm = (const float4*)g_framemean;
    float4* mom = (float4*)g_mommean;

    float4 m;
    int istart;
    if (b == 0) {
        float4 f0 = fm[c4];
        float4 f1 = fm[384 + c4];
        m = make_float4(f1.x - f0.x, f1.y - f0.y, f1.z - f0.z, f1.w - f0.w);
        mom[c4] = m;
        istart = 1;
    } else {
        int istar = s - 1;
        int jlo = istar - (SCAN_WIN - 1); if (jlo < 0) jlo = 0;
        float w = 0.5f;
        float4 acc = make_float4(0.f, 0.f, 0.f, 0.f);
#pragma unroll 8
        for (int j = istar; j >= jlo; j--) {
            float4 fa = fm[(size_t)j * 384 + c4];
            float4 fb = fm[(size_t)(j + 1) * 384 + c4];
            acc.x = fmaf(w, fb.x - fa.x, acc.x);
            acc.y = fmaf(w, fb.y - fa.y, acc.y);
            acc.z = fmaf(w, fb.z - fa.z, acc.z);
            acc.w = fmaf(w, fb.w - fa.w, acc.w);
            if (j >= 2) w *= 0.5f;            // diff[0] shares diff[1]'s weight
        }
        m = acc;
        istart = s;
    }
#pragma unroll
    for (int i0 = 0; i0 < SCAN_SEG; i0++) {
        int i = (b == 0) ? (istart + i0) : (s + i0);
        if (i >= NM1) break;
        if (b == 0 && i0 >= SCAN_SEG - 1 && istart + i0 >= SCAN_SEG) break;
        if (i < istart) continue;
        float4 fa = fm[(size_t)i * 384 + c4];
        float4 fb = fm[(size_t)(i + 1) * 384 + c4];
        m.x = 0.5f * (fb.x - fa.x) + 0.5f * m.x;
        m.y = 0.5f * (fb.y - fa.y) + 0.5f * m.y;
        m.z = 0.5f * (fb.z - fa.z) + 0.5f * m.z;
        m.w = 0.5f * (fb.w - fa.w) + 0.5f * m.w;
        mom[(size_t)i * 384 + c4] = m;
    }
}

// ---------------------------------------------------------------------------
// tf32 tensor-core split-K GEMM, 3-term hi/lo compensation (fp32-accurate).
// A staged RAW in smem (hi/lo split post-LDS in regs) -> 52KB smem/block.
// BM=64, BN=64, BK=32, 256 threads, 8 warps (4m x 2n), warp = 16x32 out.
// ---------------------------------------------------------------------------
#define GBM 64
#define GBN 64
#define GBK 32
#define ASTR (GBK + 4)    // 36
#define BSTR (GBN + 4)    // 68

__global__ void __launch_bounds__(256) gemm_tf32_splitk(
    const float* __restrict__ A, const float* __restrict__ B,
    float* __restrict__ Cpart, int M, int N, int K)
{
    __shared__ float As_raw[2][GBM][ASTR];
    __shared__ float Bs_hi[2][GBK][BSTR];
    __shared__ float Bs_lo[2][GBK][BSTR];

    int tid = threadIdx.x;
    int lane = tid & 31, wid = tid >> 5;
    int wm = (wid & 3) * 16;
    int wn = (wid >> 2) * 32;
    int g = lane >> 2, t = lane & 3;

    int n0 = blockIdx.x * GBN;
    int m0 = blockIdx.y * GBM;
    int kchunk = K / gridDim.z;
    int k0 = blockIdx.z * kchunk;
    int ksteps = kchunk / GBK;

    int ar = tid >> 2;              // 0..63
    int ac = (tid & 3) * 4;         // 0,4,8,12 ; second at +16
    int br = tid >> 4;              // 0..15    ; second at +16
    int bc = (tid & 15) * 4;        // 0..60

    bool a_ok = (m0 + ar) < M;
    const float* Aptr = A + (size_t)(m0 + ar) * K + k0;
    const float* Bptr = B + (size_t)(k0 + br) * N + n0 + bc;

    float d[4][4];
#pragma unroll
    for (int j = 0; j < 4; j++)
#pragma unroll
        for (int i = 0; i < 4; i++) d[j][i] = 0.f;

    float4 a_pre0, a_pre1, b_pre0, b_pre1;

    auto fetch = [&](int kt) {
        const float* ap = Aptr + kt * GBK;
        a_pre0 = a_ok ? *(const float4*)(ap + ac)      : make_float4(0.f, 0.f, 0.f, 0.f);
        a_pre1 = a_ok ? *(const float4*)(ap + ac + 16) : make_float4(0.f, 0.f, 0.f, 0.f);
        const float* bp = Bptr + (size_t)kt * GBK * N;
        b_pre0 = *(const float4*)bp;
        b_pre1 = *(const float4*)(bp + (size_t)16 * N);
    };
    auto stage = [&](int buf) {
        *(float4*)&As_raw[buf][ar][ac]      = a_pre0;
        *(float4*)&As_raw[buf][ar][ac + 16] = a_pre1;
        float4 bv = b_pre0;
        float p0 = f2tf32(bv.x), p1 = f2tf32(bv.y), p2 = f2tf32(bv.z), p3 = f2tf32(bv.w);
        *(float4*)&Bs_hi[buf][br][bc] = make_float4(p0, p1, p2, p3);
        *(float4*)&Bs_lo[buf][br][bc] =
            make_float4(f2tf32(bv.x - p0), f2tf32(bv.y - p1),
                        f2tf32(bv.z - p2), f2tf32(bv.w - p3));
        bv = b_pre1;
        p0 = f2tf32(bv.x); p1 = f2tf32(bv.y); p2 = f2tf32(bv.z); p3 = f2tf32(bv.w);
        *(float4*)&Bs_hi[buf][br + 16][bc] = make_float4(p0, p1, p2, p3);
        *(float4*)&Bs_lo[buf][br + 16][bc] =
            make_float4(f2tf32(bv.x - p0), f2tf32(bv.y - p1),
                        f2tf32(bv.z - p2), f2tf32(bv.w - p3));
    };

    fetch(0);
    stage(0);
    __syncthreads();

    for (int kt = 0; kt < ksteps; kt++) {
        int cur = kt & 1;
        if (kt + 1 < ksteps) fetch(kt + 1);
#pragma unroll
        for (int ks = 0; ks < 4; ks++) {
            int kk = ks * 8;
            float araw[4];
            araw[0] = As_raw[cur][wm + g    ][kk + t    ];
            araw[1] = As_raw[cur][wm + g + 8][kk + t    ];
            araw[2] = As_raw[cur][wm + g    ][kk + t + 4];
            araw[3] = As_raw[cur][wm + g + 8][kk + t + 4];
            uint32_t ah[4], al[4];
#pragma unroll
            for (int i = 0; i < 4; i++) {
                float hi = f2tf32(araw[i]);
                ah[i] = __float_as_uint(hi);
                al[i] = __float_as_uint(f2tf32(araw[i] - hi));
            }
#pragma unroll
            for (int j = 0; j < 4; j++) {
                int n = wn + j * 8 + g;
                uint32_t bh0 = __float_as_uint(Bs_hi[cur][kk + t    ][n]);
                uint32_t bh1 = __float_as_uint(Bs_hi[cur][kk + t + 4][n]);
                uint32_t bl0 = __float_as_uint(Bs_lo[cur][kk + t    ][n]);
                uint32_t bl1 = __float_as_uint(Bs_lo[cur][kk + t + 4][n]);
                MMA_TF32(d[j], ah, bh0, bh1);   // hi*hi
                MMA_TF32(d[j], ah, bl0, bl1);   // hi*lo
                MMA_TF32(d[j], al, bh0, bh1);   // lo*hi
            }
        }
        if (kt + 1 < ksteps) {
            stage(cur ^ 1);
            __syncthreads();
        }
    }

    size_t MN = (size_t)M * N;
    float* Cb = Cpart + (size_t)blockIdx.z * MN;
#pragma unroll
    for (int j = 0; j < 4; j++) {
        int col = n0 + wn + j * 8 + 2 * t;
        int r0 = m0 + wm + g;
        if (r0 < M) *(float2*)&Cb[(size_t)r0 * N + col] = make_float2(d[j][0], d[j][1]);
        int r1 = r0 + 8;
        if (r1 < M) *(float2*)&Cb[(size_t)r1 * N + col] = make_float2(d[j][2], d[j][3]);
    }
}

// ---------------------------------------------------------------------------
// Single-term tf32 split-K GEMM (thumbnail only; analog output, ~2e-4 err).
// ---------------------------------------------------------------------------
__global__ void __launch_bounds__(256) gemm_tf32_1term(
    const float* __restrict__ A, const float* __restrict__ B,
    float* __restrict__ Cpart, int M, int N, int K)
{
    __shared__ float As_raw[2][GBM][ASTR];
    __shared__ float Bs_hi[2][GBK][BSTR];

    int tid = threadIdx.x;
    int lane = tid & 31, wid = tid >> 5;
    int wm = (wid & 3) * 16;
    int wn = (wid >> 2) * 32;
    int g = lane >> 2, t = lane & 3;

    int n0 = blockIdx.x * GBN;
    int m0 = blockIdx.y * GBM;
    int kchunk = K / gridDim.z;
    int k0 = blockIdx.z * kchunk;
    int ksteps = kchunk / GBK;

    int ar = tid >> 2;
    int ac = (tid & 3) * 4;
    int br = tid >> 4;
    int bc = (tid & 15) * 4;

    bool a_ok = (m0 + ar) < M;
    const float* Aptr = A + (size_t)(m0 + ar) * K + k0;
    const float* Bptr = B + (size_t)(k0 + br) * N + n0 + bc;

    float d[4][4];
#pragma unroll
    for (int j = 0; j < 4; j++)
#pragma unroll
        for (int i = 0; i < 4; i++) d[j][i] = 0.f;

    float4 a_pre0, a_pre1, b_pre0, b_pre1;

    auto fetch = [&](int kt) {
        const float* ap = Aptr + kt * GBK;
        a_pre0 = a_ok ? *(const float4*)(ap + ac)      : make_float4(0.f, 0.f, 0.f, 0.f);
        a_pre1 = a_ok ? *(const float4*)(ap + ac + 16) : make_float4(0.f, 0.f, 0.f, 0.f);
        const float* bp = Bptr + (size_t)kt * GBK * N;
        b_pre0 = *(const float4*)bp;
        b_pre1 = *(const float4*)(bp + (size_t)16 * N);
    };
    auto stage = [&](int buf) {
        *(float4*)&As_raw[buf][ar][ac]      = a_pre0;
        *(float4*)&As_raw[buf][ar][ac + 16] = a_pre1;
        *(float4*)&Bs_hi[buf][br][bc] =
            make_float4(f2tf32(b_pre0.x), f2tf32(b_pre0.y), f2tf32(b_pre0.z), f2tf32(b_pre0.w));
        *(float4*)&Bs_hi[buf][br + 16][bc] =
            make_float4(f2tf32(b_pre1.x), f2tf32(b_pre1.y), f2tf32(b_pre1.z), f2tf32(b_pre1.w));
    };

    fetch(0);
    stage(0);
    __syncthreads();

    for (int kt = 0; kt < ksteps; kt++) {
        int cur = kt & 1;
        if (kt + 1 < ksteps) fetch(kt + 1);
#pragma unroll
        for (int ks = 0; ks < 4; ks++) {
            int kk = ks * 8;
            uint32_t ah[4];
            ah[0] = __float_as_uint(f2tf32(As_raw[cur][wm + g    ][kk + t    ]));
            ah[1] = __float_as_uint(f2tf32(As_raw[cur][wm + g + 8][kk + t    ]));
            ah[2] = __float_as_uint(f2tf32(As_raw[cur][wm + g    ][kk + t + 4]));
            ah[3] = __float_as_uint(f2tf32(As_raw[cur][wm + g + 8][kk + t + 4]));
#pragma unroll
            for (int j = 0; j < 4; j++) {
                int n = wn + j * 8 + g;
                uint32_t bh0 = __float_as_uint(Bs_hi[cur][kk + t    ][n]);
                uint32_t bh1 = __float_as_uint(Bs_hi[cur][kk + t + 4][n]);
                MMA_TF32(d[j], ah, bh0, bh1);
            }
        }
        if (kt + 1 < ksteps) {
            stage(cur ^ 1);
            __syncthreads();
        }
    }

    size_t MN = (size_t)M * N;
    float* Cb = Cpart + (size_t)blockIdx.z * MN;
#pragma unroll
    for (int j = 0; j < 4; j++) {
        int col = n0 + wn + j * 8 + 2 * t;
        int r0 = m0 + wm + g;
        if (r0 < M) *(float2*)&Cb[(size_t)r0 * N + col] = make_float2(d[j][0], d[j][1]);
        int r1 = r0 + 8;
        if (r1 < M) *(float2*)&Cb[(size_t)r1 * N + col] = make_float2(d[j][2], d[j][3]);
    }
}

// ---------------------------------------------------------------------------
// Fused: combine split-K partials (+b_agg) -> LayerNorm -> g_xn.
// ---------------------------------------------------------------------------
__global__ void __launch_bounds__(512) ln_combine_kernel(
    const float* __restrict__ part, const float* __restrict__ b_agg,
    const float* __restrict__ ln_g, const float* __restrict__ ln_b)
{
    int row = blockIdx.x;
    const size_t MN = (size_t)NM1 * DD;
    const float* base = part + (size_t)row * DD;
    float v[3];
    float s = 0.f, ss = 0.f;
#pragma unroll
    for (int c = 0; c < 3; c++) {
        int col = threadIdx.x + c * 512;
        float a = b_agg[col];
#pragma unroll
        for (int z = 0; z < SPLITK; z++) a += base[(size_t)z * MN + col];
        v[c] = a;
        s += a;
        ss = fmaf(a, a, ss);
    }
    __shared__ float sh1[16], sh2[16];
    int lane = threadIdx.x & 31, w = threadIdx.x >> 5;
#pragma unroll
    for (int o = 16; o; o >>= 1) {
        s  += __shfl_xor_sync(0xFFFFFFFFu, s, o);
        ss += __shfl_xor_sync(0xFFFFFFFFu, ss, o);
    }
    if (lane == 0) { sh1[w] = s; sh2[w] = ss; }
    __syncthreads();
    if (w == 0) {
        s  = (lane < 16) ? sh1[lane] : 0.f;
        ss = (lane < 16) ? sh2[lane] : 0.f;
#pragma unroll
        for (int o = 8; o; o >>= 1) {
            s  += __shfl_xor_sync(0xFFFFFFFFu, s, o);
            ss += __shfl_xor_sync(0xFFFFFFFFu, ss, o);
        }
        if (lane == 0) { sh1[0] = s; sh2[0] = ss; }
    }
    __syncthreads();
    float mu  = sh1[0] * (1.0f / DD);
    float var = sh2[0] * (1.0f / DD) - mu * mu;
    float rstd = rsqrtf(var + 1e-5f);
#pragma unroll
    for (int c = 0; c < 3; c++) {
        int col = threadIdx.x + c * 512;
        g_xn[row * DD + col] = (v[c] - mu) * rstd * ln_g[col] + ln_b[col];
    }
}

// ---------------------------------------------------------------------------
// Fused: combine split-K partials (+b1) -> GELU -> dot W2 (+b2) ->
// gate logits (out) + gumbel-softmax y (g_y).
// ---------------------------------------------------------------------------
__global__ void __launch_bounds__(512) gate_combine_kernel(
    const float* __restrict__ part, const float* __restrict__ b1,
    const float* __restrict__ W2, const float* __restrict__ b2,
    const float* __restrict__ gu, float* __restrict__ out)
{
    int row = blockIdx.x;
    const size_t MN = (size_t)NM1 * DD;
    const float* base = part + (size_t)row * DD;
    float s0 = 0.f, s1 = 0.f;
#pragma unroll
    for (int c = 0; c < 3; c++) {
        int col = threadIdx.x + c * 512;
        float a = b1[col];
#pragma unroll
        for (int z = 0; z < SPLITK; z++) a += base[(size_t)z * MN + col];
        a = 0.5f * a * (1.0f + erff(a * 0.70710678118654752f));   // exact GELU
        float2 w2 = *(const float2*)&W2[col * 2];
        s0 = fmaf(a, w2.x, s0);
        s1 = fmaf(a, w2.y, s1);
    }
    __shared__ float sh0[16], sh1w[16];
    int lane = threadIdx.x & 31, w = threadIdx.x >> 5;
#pragma unroll
    for (int o = 16; o; o >>= 1) {
        s0 += __shfl_xor_sync(0xFFFFFFFFu, s0, o);
        s1 += __shfl_xor_sync(0xFFFFFFFFu, s1, o);
    }
    if (lane == 0) { sh0[w] = s0; sh1w[w] = s1; }
    __syncthreads();
    if (threadIdx.x == 0) {
        float l0 = b2[0], l1 = b2[1];
#pragma unroll
        for (int i = 0; i < 16; i++) { l0 += sh0[i]; l1 += sh1w[i]; }
        out[OUT_GATE + row * 2 + 0] = l0;
        out[OUT_GATE + row * 2 + 1] = l1;
        float u0 = gu[row * 2 + 0], u1 = gu[row * 2 + 1];
        float g0 = -logf(-logf(u0 + 1e-20f) + 1e-20f);
        float g1 = -logf(-logf(u1 + 1e-20f) + 1e-20f);
        float a0 = (l0 + g0 * 0.1f) * 2.0f;   // / TEMP(0.5)
        float a1 = (l1 + g1 * 0.1f) * 2.0f;
        float mx = fmaxf(a0, a1);
        float e0 = expf(a0 - mx), e1 = expf(a1 - mx);
        g_y[row] = e1 / (e0 + e1);
    }
}

// ---------------------------------------------------------------------------
// pooled + fused top-8:
// Warp 0 of every block recomputes the (deterministic) top-8 selection from
// g_y via warp shuffles + ballot ranking; block (0,0) also writes z_hard to
// out. Then all 256 threads gather the 9 selected frames from vf.
// grid (64 groups, 3 col-chunks), 256 threads (2 row-halves x 128 cols).
// ---------------------------------------------------------------------------
__global__ void __launch_bounds__(256) pooled_kernel(const float* __restrict__ vf,
                                                     float* __restrict__ out)
{
    __shared__ int   s_sel[PG];
    __shared__ float s_w[PG];
    __shared__ float s_scale;
    __shared__ float4 s_acc[128];

    int tid = threadIdx.x;
    int lane = tid & 31;
    int wid = tid >> 5;

    if (wid == 0) {
        // each lane owns elements e = lane*4 + j (j=0..3); e=127 padded -inf
        float yv[4]; int tk[4];
#pragma unroll
        for (int j = 0; j < 4; j++) {
            int e = lane * 4 + j;
            yv[j] = (e < NM1) ? g_y[e] : -1e30f;
            tk[j] = 0;
        }
        // 8 rounds of argmax (value desc, index asc on ties)
        for (int it = 0; it < NCUBES; it++) {
            float bv = -1e30f; int bi = 1 << 30;
#pragma unroll
            for (int j = 0; j < 4; j++) {
                int e = lane * 4 + j;
                if (!tk[j] && (yv[j] > bv || (yv[j] == bv && e < bi))) { bv = yv[j]; bi = e; }
            }
#pragma unroll
            for (int o = 16; o; o >>= 1) {
                float v2 = __shfl_xor_sync(0xFFFFFFFFu, bv, o);
                int   i2 = __shfl_xor_sync(0xFFFFFFFFu, bi, o);
                if (v2 > bv || (v2 == bv && i2 < bi)) { bv = v2; bi = i2; }
            }
            if ((bi >> 2) == lane) tk[bi & 3] = 1;
        }
        // rank taken elements by index via ballots -> ordered selection list
        unsigned bal[4];
#pragma unroll
        for (int j = 0; j < 4; j++) bal[j] = __ballot_sync(0xFFFFFFFFu, tk[j] != 0);
        unsigned lowm = (1u << lane) - 1u;
        float zs = 0.f;
#pragma unroll
        for (int j = 0; j < 4; j++) {
            if (tk[j]) {
                int rank = 0;
#pragma unroll
                for (int j2 = 0; j2 < 4; j2++) {
                    rank += __popc(bal[j2] & lowm);
                    if (j2 < j) rank += (bal[j2] >> lane) & 1u;
                }
                float z = (1.0f - yv[j]) + yv[j];
                s_sel[1 + rank] = lane * 4 + j + 1;   // frame index
                s_w[1 + rank] = z;
                zs += z;
            }
        }
#pragma unroll
        for (int o = 16; o; o >>= 1) zs += __shfl_xor_sync(0xFFFFFFFFu, zs, o);
        if (lane == 0) {
            s_sel[0] = 0; s_w[0] = 1.0f;
            s_scale = 1.0f / ((float)PG * (1.0f + zs));
        }
        // z_hard output (once)
        if (blockIdx.x == 0 && blockIdx.y == 0) {
            if (lane == 0) out[OUT_Z] = 1.0f;
#pragma unroll
            for (int j = 0; j < 4; j++) {
                int e = lane * 4 + j;
                if (e < NM1)
                    out[OUT_Z + 1 + e] = tk[j] ? ((1.0f - yv[j]) + yv[j]) : 0.0f;
            }
        }
    }
    __syncthreads();

    int g = blockIdx.x;
    int col = blockIdx.y * 128 + (tid & 127);
    int h = tid >> 7;                          // row-half 0/1
    float4 acc = make_float4(0.f, 0.f, 0.f, 0.f);
    for (int k = h; k < PG; k += 2) {
        int n = s_sel[k];
        float w = s_w[k];
        const float4* base =
            (const float4*)(vf + ((size_t)n * PP + (size_t)g * PG) * DD) + col;
#pragma unroll
        for (int r = 0; r < PG; r++) {
            float4 v = base[(size_t)r * (DD / 4)];
            acc.x = fmaf(w, v.x, acc.x);
            acc.y = fmaf(w, v.y, acc.y);
            acc.z = fmaf(w, v.z, acc.z);
            acc.w = fmaf(w, v.w, acc.w);
        }
    }
    if (h == 1) s_acc[tid & 127] = acc;
    __syncthreads();
    if (h == 0) {
        float4 o = s_acc[tid];
        float sc = s_scale;
        acc.x = (acc.x + o.x) * sc;
        acc.y = (acc.y + o.y) * sc;
        acc.z = (acc.z + o.z) * sc;
        acc.w = (acc.w + o.w) * sc;
        ((float4*)(g_pooled + g * DD))[col] = acc;
    }
}

// ---------------------------------------------------------------------------
// Thumbnail combine (SPLITK3 partials): float2-vectorized
// ---------------------------------------------------------------------------
__global__ void __launch_bounds__(256) combine_th_kernel(
    const float* __restrict__ part, const float* __restrict__ bias,
    float* __restrict__ dst)
{
    int idx = blockIdx.x * blockDim.x + threadIdx.x;   // float2 index
    const int total2 = NQ * LM / 2;
    if (idx >= total2) return;
    int col2 = idx & (LM / 2 - 1);
    float2 v = *(const float2*)&bias[col2 * 2];
    const float2* p2 = (const float2*)part;
#pragma unroll
    for (int z = 0; z < SPLITK3; z++) {
        float2 a = p2[(size_t)z * total2 + idx];
        v.x += a.x; v.y += a.y;
    }
    *(float2*)&dst[idx * 2] = v;
}

// ---------------------------------------------------------------------------
// launch
// ---------------------------------------------------------------------------
extern "C" void kernel_launch(void* const* d_in, const int* in_sizes, int n_in,
                              void* d_out, int out_size) {
    const float* vf    = (const float*)d_in[0];
    const float* gu    = (const float*)d_in[1];
    const float* W_agg = (const float*)d_in[2];
    const float* b_agg = (const float*)d_in[3];
    const float* ln_g  = (const float*)d_in[4];
    const float* ln_b  = (const float*)d_in[5];
    const float* W1    = (const float*)d_in[6];
    const float* b1    = (const float*)d_in[7];
    const float* W2    = (const float*)d_in[8];
    const float* b2    = (const float*)d_in[9];
    const float* W_th  = (const float*)d_in[10];
    const float* b_th  = (const float*)d_in[11];
    float* out = (float*)d_out;

    float* d_part;   cudaGetSymbolAddress((void**)&d_part,   g_part);
    float* d_mom;    cudaGetSymbolAddress((void**)&d_mom,    g_mommean);
    float* d_xn;     cudaGetSymbolAddress((void**)&d_xn,     g_xn);
    float* d_pooled; cudaGetSymbolAddress((void**)&d_pooled, g_pooled);

    // 1) stream video features once -> framemean
    framesum_kernel<<<dim3(NF, 3), 256>>>(vf);
    // 2) windowed-parallel momentum EMA scan
    scan_kernel<<<16, 384>>>();
    // 3) feat partials = mommean @ W_agg   (tf32 TC 3-term, split-K=8)
    gemm_tf32_splitk<<<dim3(DD / GBN, 2, SPLITK), 256>>>(d_mom, W_agg, d_part, NM1, DD, DD);
    // 4) combine + bias + LayerNorm -> xn
    ln_combine_kernel<<<NM1, 512>>>(d_part, b_agg, ln_g, ln_b);
    // 5) h partials = xn @ W1   (3-term)
    gemm_tf32_splitk<<<dim3(DD / GBN, 2, SPLITK), 256>>>(d_xn, W1, d_part, NM1, DD, DD);
    // 6) combine + bias + GELU + gate head + gumbel y
    gate_combine_kernel<<<NM1, 512>>>(d_part, b1, W2, b2, gu, out);
    // 7) pooled (fused top-8 + z_hard) from selected frames
    pooled_kernel<<<dim3(NQ, 3), 256>>>(vf, out);
    // 8) thumbnail partials = pooled @ W_th  (single-term tf32, split-K=4)
    gemm_tf32_1term<<<dim3(LM / GBN, 1, SPLITK3), 256>>>(d_pooled, W_th, d_part, NQ, LM, DD);
    // 9) combine + bias -> out
    combine_th_kernel<<<(NQ * LM / 2 + 255) / 256, 256>>>(d_part, b_th, out + OUT_TH);
}